// round 8
// baseline (speedup 1.0000x reference)
#include <cuda_runtime.h>

#define NUQ 500000
#define NIQ 100000
#define FQ  300
#define DQ  64
#define EQ  2000000
#define ELQ 1000000
#define NB_SCAN 123            // ceil(NUQ / 4096)
#define UPB 64                 // users per block in fused user layer

// ---------------- scratch (device globals; no allocations allowed) -------------
__device__ __align__(16) float g_xi  [NIQ * DQ];   // item input features
__device__ __align__(16) float g_itT [NIQ * DQ];   // transformed item table (x_i @ Wl_iu)
__device__ __align__(16) float g_aggi[NIQ * DQ];   // item aggregate of raw user rows
__device__ __align__(16) float g_hu  [NUQ * DQ];
__device__ __align__(16) float g_hi  [NIQ * DQ];
__device__ __align__(16) float g_hu2 [NUQ * DQ];
__device__ __align__(16) float g_hi2 [NIQ * DQ];

// CSR-by-src machinery
__device__ int g_cnt   [NUQ + NIQ];   // [0,NUQ): user degree, [NUQ,..): item degree
__device__ int g_pre   [NUQ];
__device__ int g_rowptr[NUQ];
__device__ int g_cursor[NUQ];
__device__ int g_bsum  [128];
__device__ int g_dsts  [EQ];

// ---------------- histogram ----------------------------------------------------
__global__ void k_hist(const int* __restrict__ src, const int* __restrict__ dst) {
    int i = blockIdx.x * blockDim.x + threadIdx.x;
    if (i < EQ) {
        atomicAdd(&g_cnt[src[i]], 1);
        atomicAdd(&g_cnt[NUQ + dst[i]], 1);
    }
}

// ---------------- hierarchical exclusive scan of user degrees ------------------
__global__ __launch_bounds__(512) void k_scan1() {
    __shared__ int swarp[16];
    const int t = threadIdx.x;
    const int base = blockIdx.x * 4096 + t * 8;
    int v[8], s = 0;
    #pragma unroll
    for (int j = 0; j < 8; ++j) {
        v[j] = (base + j < NUQ) ? g_cnt[base + j] : 0;
        s += v[j];
    }
    const int lane = t & 31, w = t >> 5;
    int x = s;
    #pragma unroll
    for (int off = 1; off < 32; off <<= 1) {
        int y = __shfl_up_sync(0xffffffffu, x, off);
        if (lane >= off) x += y;
    }
    if (lane == 31) swarp[w] = x;
    __syncthreads();
    if (w == 0) {
        int y = (lane < 16) ? swarp[lane] : 0;
        #pragma unroll
        for (int off = 1; off < 16; off <<= 1) {
            int z = __shfl_up_sync(0xffffffffu, y, off);
            if (lane >= off) y += z;
        }
        if (lane < 16) swarp[lane] = y;
    }
    __syncthreads();
    int run = (w > 0 ? swarp[w - 1] : 0) + (x - s);
    #pragma unroll
    for (int j = 0; j < 8; ++j) {
        if (base + j < NUQ) g_pre[base + j] = run;
        run += v[j];
    }
    if (t == 0) g_bsum[blockIdx.x] = swarp[15];
}

// scan2+scan3 merged: each block sums its 4096-group's bsum prefix, then offsets
__global__ void k_scan23() {
    __shared__ int s_off;
    if (threadIdx.x == 0) {
        int blk = blockIdx.x >> 4;   // which 4096-group this 256-block belongs to
        int a = 0;
        for (int j = 0; j < blk; ++j) a += g_bsum[j];
        s_off = a;
    }
    __syncthreads();
    int i = blockIdx.x * blockDim.x + threadIdx.x;
    if (i < NUQ) {
        int r = g_pre[i] + s_off;
        g_rowptr[i] = r;
        g_cursor[i] = r;
    }
}

__global__ void k_place(const int* __restrict__ src, const int* __restrict__ dst) {
    int i = blockIdx.x * blockDim.x + threadIdx.x;
    if (i < EQ) {
        int s = src[i];
        int pos = atomicAdd(&g_cursor[s], 1);
        g_dsts[pos] = dst[i];
    }
}

// ---------------- helpers -------------------------------------------------------
__device__ __forceinline__ unsigned long long dup_f(float f) {
    unsigned int b = __float_as_uint(f);
    return ((unsigned long long)b << 32) | b;
}
__device__ __forceinline__ float lo_f(unsigned long long v) {
    return __uint_as_float((unsigned int)(v & 0xffffffffull));
}
__device__ __forceinline__ float hi_f(unsigned long long v) {
    return __uint_as_float((unsigned int)(v >> 32));
}
__device__ __forceinline__ unsigned long long d2u(double d) {
    return (unsigned long long)__double_as_longlong(d);
}
__device__ __forceinline__ void red_add_v4(float* p, float4 v) {
    asm volatile("red.global.add.v4.f32 [%0], {%1, %2, %3, %4};"
                 :: "l"(p), "f"(v.x), "f"(v.y), "f"(v.z), "f"(v.w) : "memory");
}

// ---------------- fused item input GEMM -----------------------------------------
// GEMM1: xi = item_x @ W + b   (K=300, 5 chunks of 60), f32x2 row-pair packed.
// GEMM2: itT1 = xi @ Wl1       (K=64), same tile, from smem-packed xi pairs.
// Tile 128 rows x 64 cols, 128 threads: tx=t&7 (cols tx+8ci), ty=t>>3 (rows ty*8..+7
// as 4 packed row-pairs).
__global__ __launch_bounds__(128) void k_item_gemm_f(
    const float* __restrict__ X, const float* __restrict__ W,
    const float* __restrict__ bias, const float* __restrict__ Wl1)
{
    extern __shared__ float sm[];
    double* sWd  = (double*)sm;                 // [0,32KB): W chunk dup / Wl1 dup
    float*  saT  = sm + 8192;                   // [32KB,..): X chunk transposed (pitch 136)
    double* sxiP = (double*)(sm + 8192);        // later: xi packed pairs, pitch 65

    const int tid = threadIdx.x;
    const int tx = tid & 7;
    const int ty = tid >> 3;
    const int row0 = blockIdx.x * 128;

    unsigned long long acc[4][8];
    #pragma unroll
    for (int ci = 0; ci < 8; ++ci) {
        unsigned long long bp = dup_f(bias[tx + 8 * ci]);
        #pragma unroll
        for (int j = 0; j < 4; ++j) acc[j][ci] = bp;
    }

    for (int k0 = 0; k0 < FQ; k0 += 60) {
        __syncthreads();
        for (int i = tid; i < 3840; i += 128)
            sWd[i] = __longlong_as_double((long long)dup_f(W[k0 * 64 + i]));
        for (int i = tid; i < 1920; i += 128) {
            int r = i / 15, c4 = i - r * 15;
            int grow = row0 + r;
            float4 v = make_float4(0.f, 0.f, 0.f, 0.f);
            if (grow < NIQ)
                v = *(const float4*)(X + (size_t)grow * FQ + k0 + c4 * 4);
            int k = c4 * 4;
            saT[(k + 0) * 136 + r] = v.x;
            saT[(k + 1) * 136 + r] = v.y;
            saT[(k + 2) * 136 + r] = v.z;
            saT[(k + 3) * 136 + r] = v.w;
        }
        __syncthreads();

        #pragma unroll 4
        for (int k = 0; k < 60; ++k) {
            unsigned long long ap[4];
            const double* arow = (const double*)(saT + k * 136 + ty * 8);
            #pragma unroll
            for (int j = 0; j < 4; ++j) ap[j] = d2u(arow[j]);
            #pragma unroll
            for (int ci = 0; ci < 8; ++ci) {
                unsigned long long wd = d2u(sWd[k * 64 + tx + 8 * ci]);
                #pragma unroll
                for (int j = 0; j < 4; ++j)
                    asm("fma.rn.f32x2 %0, %1, %2, %0;" : "+l"(acc[j][ci]) : "l"(ap[j]), "l"(wd));
            }
        }
    }
    __syncthreads();

    // load Wl1 dup; write xi to global; pack xi pairs into smem
    for (int i = tid; i < 4096; i += 128)
        sWd[i] = __longlong_as_double((long long)dup_f(Wl1[i]));
    #pragma unroll
    for (int j = 0; j < 4; ++j) {
        int rp = ty * 4 + j;
        int r0g = row0 + 2 * rp, r1g = r0g + 1;
        #pragma unroll
        for (int ci = 0; ci < 8; ++ci) {
            int c = tx + 8 * ci;
            if (r0g < NIQ) g_xi[(size_t)r0g * 64 + c] = lo_f(acc[j][ci]);
            if (r1g < NIQ) g_xi[(size_t)r1g * 64 + c] = hi_f(acc[j][ci]);
            sxiP[c * 65 + rp] = __longlong_as_double((long long)acc[j][ci]);
        }
    }
    __syncthreads();

    // GEMM2: itT1 = xi @ Wl1 (k = 64 cols of xi)
    unsigned long long acc2[4][8];
    #pragma unroll
    for (int ci = 0; ci < 8; ++ci)
        #pragma unroll
        for (int j = 0; j < 4; ++j) acc2[j][ci] = 0ull;

    #pragma unroll 4
    for (int c = 0; c < 64; ++c) {
        unsigned long long ap[4];
        const double* arow = sxiP + c * 65 + ty * 4;
        #pragma unroll
        for (int j = 0; j < 4; ++j) ap[j] = d2u(arow[j]);
        #pragma unroll
        for (int ci = 0; ci < 8; ++ci) {
            unsigned long long wd = d2u(sWd[c * 64 + tx + 8 * ci]);
            #pragma unroll
            for (int j = 0; j < 4; ++j)
                asm("fma.rn.f32x2 %0, %1, %2, %0;" : "+l"(acc2[j][ci]) : "l"(ap[j]), "l"(wd));
        }
    }
    #pragma unroll
    for (int j = 0; j < 4; ++j) {
        int rp = ty * 4 + j;
        int r0g = row0 + 2 * rp, r1g = r0g + 1;
        #pragma unroll
        for (int ci = 0; ci < 8; ++ci) {
            int c = tx + 8 * ci;
            if (r0g < NIQ) g_itT[(size_t)r0g * 64 + c] = lo_f(acc2[j][ci]);
            if (r1g < NIQ) g_itT[(size_t)r1g * 64 + c] = hi_f(acc2[j][ci]);
        }
    }
}

// ---------------- fused user layer ----------------------------------------------
// Phase A (warp-granular work stealing over 64 users/block): half-warp per user,
// load raw user row, CSR edge loop: acc += itT[d]; RED raw row into aggi.
// Phase B: block GEMM out = act(mean + xrow @ W + b), k-pair packed f32x2.
template <bool RELU, bool L1>
__global__ __launch_bounds__(256) void k_user_layer(
    const float4* __restrict__ usrc, const int* __restrict__ nid,
    const float4* __restrict__ itabT, float* __restrict__ aggi,
    const float* __restrict__ W, const float* __restrict__ b,
    float* __restrict__ outp)
{
    extern __shared__ float sm[];
    double* sWp   = (double*)sm;           // 2048 doubles: k-pair packed W (16 KB)
    float*  sx    = sm + 4096;             // UPB x 68 raw user rows (pitch 68)
    float*  smean = sx + UPB * 68;         // UPB x 64 mean aggregates
    __shared__ int s_ctr;

    const int tid = threadIdx.x;
    if (tid == 0) s_ctr = 0;

    for (int idx = tid; idx < 2048; idx += 256) {
        int kp = idx >> 6, c = idx & 63;
        unsigned int lo = __float_as_uint(W[kp * 128 + c]);
        unsigned int hi = __float_as_uint(W[kp * 128 + 64 + c]);
        sWp[idx] = __longlong_as_double((long long)(((unsigned long long)hi << 32) | lo));
    }
    __syncthreads();

    // ---- phase A: warp steals 2 users at a time ----
    const int lane = tid & 31;
    const int q = lane & 15;
    while (true) {
        int base = 0;
        if (lane == 0) base = atomicAdd(&s_ctr, 2);
        base = __shfl_sync(0xffffffffu, base, 0);
        if (base >= UPB) break;
        int r = base + (lane >> 4);
        bool valid = (r < UPB);
        int u = blockIdx.x * UPB + r;
        float4 xr  = make_float4(0.f, 0.f, 0.f, 0.f);
        float4 acc = make_float4(0.f, 0.f, 0.f, 0.f);
        float rd = 0.f;
        if (valid && u < NUQ) {
            int row = L1 ? __ldg(&nid[u]) : u;
            xr = usrc[(size_t)row * 16 + q];
            int beg = __ldg(&g_rowptr[u]);
            int cnt = __ldg(&g_cnt[u]);
            for (int e = beg; e < beg + cnt; ++e) {
                int d = __ldg(&g_dsts[e]);
                float4 iv = itabT[(size_t)d * 16 + q];
                acc.x += iv.x; acc.y += iv.y; acc.z += iv.z; acc.w += iv.w;
                red_add_v4(aggi + (size_t)d * 64 + q * 4, xr);
            }
            rd = 1.f / fmaxf((float)cnt, 1.f);
        }
        if (valid) {
            *(float4*)&smean[r * 64 + q * 4] = make_float4(acc.x * rd, acc.y * rd,
                                                           acc.z * rd, acc.w * rd);
            *(float4*)&sx[r * 68 + q * 4] = xr;
        }
    }
    __syncthreads();

    // ---- phase B: GEMM 64x64x64, k-pair f32x2 ----
    const int cg = tid & 15, rg = tid >> 4;
    const int c0 = cg * 4, r0 = rg * 4;

    unsigned long long acc2[4][4];
    #pragma unroll
    for (int j = 0; j < 4; ++j)
        #pragma unroll
        for (int c = 0; c < 4; ++c) acc2[j][c] = 0ull;

    #pragma unroll 8
    for (int kp = 0; kp < 32; ++kp) {
        unsigned long long a2[4];
        #pragma unroll
        for (int j = 0; j < 4; ++j)
            a2[j] = d2u(*(const double*)&sx[(r0 + j) * 68 + 2 * kp]);
        double2 w01 = *(const double2*)&sWp[kp * 64 + c0];
        double2 w23 = *(const double2*)&sWp[kp * 64 + c0 + 2];
        unsigned long long w2[4];
        w2[0] = d2u(w01.x); w2[1] = d2u(w01.y);
        w2[2] = d2u(w23.x); w2[3] = d2u(w23.y);
        #pragma unroll
        for (int j = 0; j < 4; ++j)
            #pragma unroll
            for (int c = 0; c < 4; ++c)
                asm("fma.rn.f32x2 %0, %1, %2, %0;" : "+l"(acc2[j][c]) : "l"(a2[j]), "l"(w2[c]));
    }

    const float4 bv = *(const float4*)(b + c0);
    #pragma unroll
    for (int j = 0; j < 4; ++j) {
        int u = blockIdx.x * UPB + r0 + j;
        if (u < NUQ) {
            float4 m = *(const float4*)&smean[(r0 + j) * 64 + c0];
            float o0 = lo_f(acc2[j][0]) + hi_f(acc2[j][0]) + m.x + bv.x;
            float o1 = lo_f(acc2[j][1]) + hi_f(acc2[j][1]) + m.y + bv.y;
            float o2 = lo_f(acc2[j][2]) + hi_f(acc2[j][2]) + m.z + bv.z;
            float o3 = lo_f(acc2[j][3]) + hi_f(acc2[j][3]) + m.w + bv.w;
            if (RELU) {
                o0 = fmaxf(o0, 0.f); o1 = fmaxf(o1, 0.f);
                o2 = fmaxf(o2, 0.f); o3 = fmaxf(o3, 0.f);
            }
            *(float4*)&outp[(size_t)u * 64 + c0] = make_float4(o0, o1, o2, o3);
        }
    }
}

// ---------------- item combine (dual GEMM) + optional fused next-layer xform ----
// out = act((agg/deg) @ Wl + x @ Wr + b); if XF: itT = out @ Wn
template <bool RELU, bool XF>
__global__ __launch_bounds__(128) void k_combine_i(
    int n, const float* __restrict__ agg, const int* __restrict__ deg,
    const float* __restrict__ x, const float* __restrict__ Wl,
    const float* __restrict__ Wr, const float* __restrict__ b,
    float* __restrict__ out, const float* __restrict__ Wn,
    float* __restrict__ itT)
{
    extern __shared__ float sm[];
    float*  sWl = sm;
    float*  sWr = sm + 4096;
    float*  sB  = sm + 8192;
    float*  saT = sm + 8192 + 64;
    float*  sxT = saT + 64 * 68;
    double* sWd = (double*)sm;                  // phase-2: Wn dup (4096 doubles)
    double* sP  = (double*)(sm + 8192 + 64);    // phase-2: out pairs, pitch 33

    const int tid = threadIdx.x;
    const int tx = tid & 15;
    const int ty = tid >> 4;
    const int row0 = blockIdx.x * 64;

    for (int i = tid; i < 4096; i += 128) { sWl[i] = Wl[i]; sWr[i] = Wr[i]; }
    if (tid < 64) sB[tid] = b[tid];

    for (int i = tid; i < 1024; i += 128) {
        int r = i >> 4, c4 = i & 15;
        int grow = row0 + r;
        float4 av, xv;
        float rd = 1.f;
        if (grow < n) {
            av = ((const float4*)agg)[(size_t)grow * 16 + c4];
            xv = ((const float4*)x)[(size_t)grow * 16 + c4];
            rd = 1.f / fmaxf((float)deg[grow], 1.f);
        } else {
            av = make_float4(0.f, 0.f, 0.f, 0.f);
            xv = av;
        }
        int c = c4 * 4;
        saT[(c + 0) * 68 + r] = av.x * rd;
        saT[(c + 1) * 68 + r] = av.y * rd;
        saT[(c + 2) * 68 + r] = av.z * rd;
        saT[(c + 3) * 68 + r] = av.w * rd;
        sxT[(c + 0) * 68 + r] = xv.x;
        sxT[(c + 1) * 68 + r] = xv.y;
        sxT[(c + 2) * 68 + r] = xv.z;
        sxT[(c + 3) * 68 + r] = xv.w;
    }
    __syncthreads();

    float acc[8][4];
    {
        float4 bv = *(const float4*)&sB[tx * 4];
        #pragma unroll
        for (int r = 0; r < 8; ++r) {
            acc[r][0] = bv.x; acc[r][1] = bv.y; acc[r][2] = bv.z; acc[r][3] = bv.w;
        }
    }

    #pragma unroll 4
    for (int k = 0; k < 64; ++k) {
        float4 a0 = *(const float4*)&saT[k * 68 + ty * 8];
        float4 a1 = *(const float4*)&saT[k * 68 + ty * 8 + 4];
        float4 wl = *(const float4*)&sWl[k * 64 + tx * 4];
        float4 x0 = *(const float4*)&sxT[k * 68 + ty * 8];
        float4 x1 = *(const float4*)&sxT[k * 68 + ty * 8 + 4];
        float4 wr = *(const float4*)&sWr[k * 64 + tx * 4];

        float ar[8] = {a0.x, a0.y, a0.z, a0.w, a1.x, a1.y, a1.z, a1.w};
        float xr[8] = {x0.x, x0.y, x0.z, x0.w, x1.x, x1.y, x1.z, x1.w};
        float wlc[4] = {wl.x, wl.y, wl.z, wl.w};
        float wrc[4] = {wr.x, wr.y, wr.z, wr.w};
        #pragma unroll
        for (int r = 0; r < 8; ++r)
            #pragma unroll
            for (int c = 0; c < 4; ++c)
                acc[r][c] += ar[r] * wlc[c] + xr[r] * wrc[c];
    }

    // relu + write
    #pragma unroll
    for (int r = 0; r < 8; ++r) {
        #pragma unroll
        for (int c = 0; c < 4; ++c)
            if (RELU) acc[r][c] = fmaxf(acc[r][c], 0.f);
        int grow = row0 + ty * 8 + r;
        if (grow < n) {
            float4 o = make_float4(acc[r][0], acc[r][1], acc[r][2], acc[r][3]);
            ((float4*)out)[(size_t)grow * 16 + tx] = o;
        }
    }

    if (XF) {
        __syncthreads();   // done reading sWl/sWr/saT/sxT
        for (int i = tid; i < 4096; i += 128)
            sWd[i] = __longlong_as_double((long long)dup_f(Wn[i]));
        // pack post-relu tile: sP[col * 33 + rowpair]
        #pragma unroll
        for (int m = 0; m < 4; ++m)
            #pragma unroll
            for (int c = 0; c < 4; ++c) {
                unsigned long long p =
                    ((unsigned long long)__float_as_uint(acc[2 * m + 1][c]) << 32)
                    | (unsigned long long)__float_as_uint(acc[2 * m][c]);
                sP[(tx * 4 + c) * 33 + (ty * 4 + m)] = __longlong_as_double((long long)p);
            }
        __syncthreads();

        // GEMM2: itT = out @ Wn. 128 threads: tx2=t&7 (cols tx2+8ci), ty2=t>>3 (2 pairs)
        const int tx2 = tid & 7, ty2 = tid >> 3;
        unsigned long long acc2[2][8];
        #pragma unroll
        for (int ci = 0; ci < 8; ++ci) { acc2[0][ci] = 0ull; acc2[1][ci] = 0ull; }

        #pragma unroll 4
        for (int c = 0; c < 64; ++c) {
            unsigned long long a20 = d2u(sP[c * 33 + ty2 * 2]);
            unsigned long long a21 = d2u(sP[c * 33 + ty2 * 2 + 1]);
            #pragma unroll
            for (int ci = 0; ci < 8; ++ci) {
                unsigned long long wd = d2u(sWd[c * 64 + tx2 + 8 * ci]);
                asm("fma.rn.f32x2 %0, %1, %2, %0;" : "+l"(acc2[0][ci]) : "l"(a20), "l"(wd));
                asm("fma.rn.f32x2 %0, %1, %2, %0;" : "+l"(acc2[1][ci]) : "l"(a21), "l"(wd));
            }
        }
        #pragma unroll
        for (int j = 0; j < 2; ++j) {
            int rp = ty2 * 2 + j;
            int r0g = row0 + 2 * rp, r1g = r0g + 1;
            #pragma unroll
            for (int ci = 0; ci < 8; ++ci) {
                int c = tx2 + 8 * ci;
                if (r0g < n) itT[(size_t)r0g * 64 + c] = lo_f(acc2[j][ci]);
                if (r1g < n) itT[(size_t)r1g * 64 + c] = hi_f(acc2[j][ci]);
            }
        }
    }
}

// ---------------- dot-product predictor ----------------------------------------
__global__ void k_predict(const float* __restrict__ hu, const float* __restrict__ hi,
                          const int* __restrict__ ls, const int* __restrict__ ld,
                          float* __restrict__ out)
{
    int t = blockIdx.x * blockDim.x + threadIdx.x;   // ELQ*8 exactly
    int e = t >> 3;
    int q = t & 7;
    int s = ls[e];
    int d = ld[e];
    const float4* hu4 = (const float4*)hu;
    const float4* hi4 = (const float4*)hi;
    float4 a0 = hu4[(size_t)s * 16 + q * 2];
    float4 a1 = hu4[(size_t)s * 16 + q * 2 + 1];
    float4 b0 = hi4[(size_t)d * 16 + q * 2];
    float4 b1 = hi4[(size_t)d * 16 + q * 2 + 1];
    float p = a0.x * b0.x + a0.y * b0.y + a0.z * b0.z + a0.w * b0.w
            + a1.x * b1.x + a1.y * b1.y + a1.z * b1.z + a1.w * b1.w;
    p += __shfl_down_sync(0xffffffffu, p, 4);
    p += __shfl_down_sync(0xffffffffu, p, 2);
    p += __shfl_down_sync(0xffffffffu, p, 1);
    if (q == 0) out[e] = p;
}

// ---------------- host orchestration -------------------------------------------
extern "C" void kernel_launch(void* const* d_in, const int* in_sizes, int n_in,
                              void* d_out, int out_size)
{
    const float* user_emb   = (const float*)d_in[0];
    const float* item_x     = (const float*)d_in[1];
    const float* item_lin_w = (const float*)d_in[2];
    const float* item_lin_b = (const float*)d_in[3];
    const float* Wl1_ui = (const float*)d_in[4];
    const float* Wr1_ui = (const float*)d_in[5];
    const float* b1_ui  = (const float*)d_in[6];
    const float* Wl1_iu = (const float*)d_in[7];
    const float* Wr1_iu = (const float*)d_in[8];
    const float* b1_iu  = (const float*)d_in[9];
    const float* Wl2_ui = (const float*)d_in[10];
    const float* Wr2_ui = (const float*)d_in[11];
    const float* b2_ui  = (const float*)d_in[12];
    const float* Wl2_iu = (const float*)d_in[13];
    const float* Wr2_iu = (const float*)d_in[14];
    const float* b2_iu  = (const float*)d_in[15];
    const int* user_node_id = (const int*)d_in[16];
    const int* esrc = (const int*)d_in[17];
    const int* edst = (const int*)d_in[18];
    const int* lsrc = (const int*)d_in[19];
    const int* ldst = (const int*)d_in[20];
    float* out = (float*)d_out;

    float *p_xi, *p_itT, *p_aggi, *p_hu, *p_hi, *p_hu2, *p_hi2;
    int *p_cnt;
    cudaGetSymbolAddress((void**)&p_xi,   g_xi);
    cudaGetSymbolAddress((void**)&p_itT,  g_itT);
    cudaGetSymbolAddress((void**)&p_aggi, g_aggi);
    cudaGetSymbolAddress((void**)&p_hu,   g_hu);
    cudaGetSymbolAddress((void**)&p_hi,   g_hi);
    cudaGetSymbolAddress((void**)&p_hu2,  g_hu2);
    cudaGetSymbolAddress((void**)&p_hi2,  g_hi2);
    cudaGetSymbolAddress((void**)&p_cnt,  g_cnt);

    const int SMEM_IG = 32768 + 33280;                          // 66048 B
    const int SMEM_CI = (8192 + 64 + 2 * 64 * 68) * 4;          // 67840 B
    const int SMEM_UL = 2048 * 8 + (UPB * 68 + UPB * 64) * 4;   // 50176 B
    cudaFuncSetAttribute(k_item_gemm_f, cudaFuncAttributeMaxDynamicSharedMemorySize, SMEM_IG);
    cudaFuncSetAttribute((const void*)k_combine_i<true, true>,   cudaFuncAttributeMaxDynamicSharedMemorySize, SMEM_CI);
    cudaFuncSetAttribute((const void*)k_combine_i<false, false>, cudaFuncAttributeMaxDynamicSharedMemorySize, SMEM_CI);
    cudaFuncSetAttribute((const void*)k_user_layer<true, true>,   cudaFuncAttributeMaxDynamicSharedMemorySize, SMEM_UL);
    cudaFuncSetAttribute((const void*)k_user_layer<false, false>, cudaFuncAttributeMaxDynamicSharedMemorySize, SMEM_UL);

    // ---- CSR build ----
    cudaMemsetAsync(p_cnt, 0, (NUQ + NIQ) * sizeof(int));
    cudaMemsetAsync(p_aggi, 0, (size_t)NIQ * DQ * sizeof(float));
    k_hist<<<(EQ + 255) / 256, 256>>>(esrc, edst);
    k_scan1<<<NB_SCAN, 512>>>();
    k_scan23<<<(NUQ + 255) / 256, 256>>>();
    k_place<<<(EQ + 255) / 256, 256>>>(esrc, edst);

    // ---- item features + layer-1 item transform (fused) ----
    k_item_gemm_f<<<(NIQ + 127) / 128, 128, SMEM_IG>>>(item_x, item_lin_w,
                                                       item_lin_b, Wl1_iu);

    const int GB_UL = (NUQ + UPB - 1) / UPB;

    // ---- layer 1 ----
    k_user_layer<true, true><<<GB_UL, 256, SMEM_UL>>>(
        (const float4*)user_emb, user_node_id, (const float4*)p_itT, p_aggi,
        Wr1_iu, b1_iu, p_hu);
    k_combine_i<true, true><<<(NIQ + 63) / 64, 128, SMEM_CI>>>(
        NIQ, p_aggi, p_cnt + NUQ, p_xi, Wl1_ui, Wr1_ui, b1_ui, p_hi, Wl2_iu, p_itT);

    // ---- layer 2 ----
    cudaMemsetAsync(p_aggi, 0, (size_t)NIQ * DQ * sizeof(float));
    k_user_layer<false, false><<<GB_UL, 256, SMEM_UL>>>(
        (const float4*)p_hu, nullptr, (const float4*)p_itT, p_aggi,
        Wr2_iu, b2_iu, p_hu2);
    k_combine_i<false, false><<<(NIQ + 63) / 64, 128, SMEM_CI>>>(
        NIQ, p_aggi, p_cnt + NUQ, p_hi, Wl2_ui, Wr2_ui, b2_ui, p_hi2, nullptr, nullptr);

    // ---- predictor ----
    k_predict<<<ELQ * 8 / 256, 256>>>(p_hu2, p_hi2, lsrc, ldst, out);
}